// round 1
// baseline (speedup 1.0000x reference)
#include <cuda_runtime.h>

#define N_NODES 100000
#define N_EDGES 1600000
#define D 64

// Scratch for aggregated messages (25.6 MB). Static __device__ array: allowed.
__device__ float g_agg[N_NODES * D];

// ---------------------------------------------------------------------------
// Kernel 1: zero the scratch accumulator (vectorized float4).
// ---------------------------------------------------------------------------
__global__ void zero_kernel() {
    int i = blockIdx.x * blockDim.x + threadIdx.x;
    int n4 = (N_NODES * D) / 4;
    if (i < n4) {
        reinterpret_cast<float4*>(g_agg)[i] = make_float4(0.f, 0.f, 0.f, 0.f);
    }
}

// ---------------------------------------------------------------------------
// Kernel 2: scatter  agg[dst][d] += w * feat[src][d]
// One thread per (edge, d). Consecutive threads cover consecutive d ->
// coalesced feature reads and coalesced atomic addresses. Edge metadata
// (src/dst/w) is read redundantly by 64 threads but broadcasts from L1/L2.
// ---------------------------------------------------------------------------
__global__ void scatter_kernel(const float* __restrict__ feat,
                               const int*   __restrict__ src,
                               const int*   __restrict__ dst,
                               const float* __restrict__ w) {
    long long idx = (long long)blockIdx.x * blockDim.x + threadIdx.x;
    if (idx >= (long long)N_EDGES * D) return;
    int e = (int)(idx >> 6);
    int d = (int)(idx & 63);
    int s = __ldg(&src[e]);
    int t = __ldg(&dst[e]);
    float wt = __ldg(&w[e]);
    float v = wt * __ldg(&feat[s * D + d]);
    atomicAdd(&g_agg[t * D + d], v);
}

// ---------------------------------------------------------------------------
// Kernel 3: out = relu(agg @ W + b)
// 256 threads/block, 16 rows/block. W held in smem padded to kill bank
// conflicts; each thread computes 4 output elements (same column c, rows
// rbase, rbase+4, rbase+8, rbase+12) so W column values are reused 4x.
// ---------------------------------------------------------------------------
#define ROWS_PER_BLOCK 16

__global__ void gemm_bias_relu_kernel(const float* __restrict__ W,
                                      const float* __restrict__ b,
                                      float* __restrict__ out) {
    __shared__ float Ws[D][D + 1];      // padded: bank = (k*65 + c) % 32 varies with c
    __shared__ float As[ROWS_PER_BLOCK][D];
    __shared__ float bs[D];

    int tid = threadIdx.x;

    // Load W (4096 floats) cooperatively.
    #pragma unroll
    for (int i = tid; i < D * D; i += 256) {
        Ws[i / D][i % D] = W[i];
    }
    if (tid < D) bs[tid] = b[tid];

    int row0 = blockIdx.x * ROWS_PER_BLOCK;

    // Load 16 agg rows (1024 floats) cooperatively, coalesced.
    #pragma unroll
    for (int i = tid; i < ROWS_PER_BLOCK * D; i += 256) {
        int r = i / D, c = i % D;
        As[r][c] = g_agg[(row0 + r) * D + c];
    }
    __syncthreads();

    int c     = tid & 63;       // output column
    int rbase = tid >> 6;       // 0..3

    float acc0 = bs[c];
    float acc1 = bs[c];
    float acc2 = bs[c];
    float acc3 = bs[c];

    #pragma unroll
    for (int k = 0; k < D; k++) {
        float wv = Ws[k][c];
        acc0 = fmaf(As[rbase + 0][k], wv, acc0);
        acc1 = fmaf(As[rbase + 4][k], wv, acc1);
        acc2 = fmaf(As[rbase + 8][k], wv, acc2);
        acc3 = fmaf(As[rbase + 12][k], wv, acc3);
    }

    out[(row0 + rbase + 0) * D + c]  = fmaxf(acc0, 0.f);
    out[(row0 + rbase + 4) * D + c]  = fmaxf(acc1, 0.f);
    out[(row0 + rbase + 8) * D + c]  = fmaxf(acc2, 0.f);
    out[(row0 + rbase + 12) * D + c] = fmaxf(acc3, 0.f);
}

// ---------------------------------------------------------------------------
// Launch
// ---------------------------------------------------------------------------
extern "C" void kernel_launch(void* const* d_in, const int* in_sizes, int n_in,
                              void* d_out, int out_size) {
    const float* features = (const float*)d_in[0];   // [N_NODES, D]
    const int*   edge_src = (const int*)  d_in[1];   // [N_EDGES]
    const int*   edge_dst = (const int*)  d_in[2];   // [N_EDGES]
    const float* edge_w   = (const float*)d_in[3];   // [N_EDGES]
    const float* W        = (const float*)d_in[4];   // [D, D]
    const float* b        = (const float*)d_in[5];   // [1, D]
    float* out = (float*)d_out;                      // [N_NODES, D]

    // 1) zero scratch
    {
        int n4 = (N_NODES * D) / 4;
        int threads = 256;
        int blocks = (n4 + threads - 1) / threads;
        zero_kernel<<<blocks, threads>>>();
    }

    // 2) scatter-add messages
    {
        long long total = (long long)N_EDGES * D;
        int threads = 256;
        long long blocks = (total + threads - 1) / threads;
        scatter_kernel<<<(unsigned int)blocks, threads>>>(features, edge_src,
                                                          edge_dst, edge_w);
    }

    // 3) dense transform + bias + relu
    {
        int blocks = (N_NODES + ROWS_PER_BLOCK - 1) / ROWS_PER_BLOCK;
        gemm_bias_relu_kernel<<<blocks, 256>>>(W, b, out);
    }
}

// round 2
// speedup vs baseline: 2.7776x; 2.7776x over previous
#include <cuda_runtime.h>

#define N_NODES 100000
#define N_EDGES 1600000
#define D 64

// Scratch for aggregated messages (25.6 MB).
__device__ float g_agg[N_NODES * D];

// ---------------------------------------------------------------------------
// Kernel 1: zero the scratch accumulator (vectorized float4).
// ---------------------------------------------------------------------------
__global__ void zero_kernel() {
    int i = blockIdx.x * blockDim.x + threadIdx.x;
    int n4 = (N_NODES * D) / 4;
    if (i < n4) {
        reinterpret_cast<float4*>(g_agg)[i] = make_float4(0.f, 0.f, 0.f, 0.f);
    }
}

// ---------------------------------------------------------------------------
// Kernel 2: scatter  agg[dst][:] += w * feat[src][:]
// 16 threads per edge, each handles 4 consecutive floats via float4
// (LDG.128 gather + RED.E.ADD.F32.V4 vector atomic). 4x fewer memory
// instructions than the scalar version; addresses stay coalesced.
// ---------------------------------------------------------------------------
__global__ __launch_bounds__(256) void scatter_kernel(
        const float* __restrict__ feat,
        const int*   __restrict__ src,
        const int*   __restrict__ dst,
        const float* __restrict__ w) {
    int idx = blockIdx.x * blockDim.x + threadIdx.x;   // over E*16 = 25.6M
    if (idx >= N_EDGES * 16) return;
    int e = idx >> 4;        // edge id
    int q = idx & 15;        // float4 chunk within the 64-wide row

    int s = __ldg(&src[e]);
    int t = __ldg(&dst[e]);
    float wt = __ldg(&w[e]);

    const float4* f4 = reinterpret_cast<const float4*>(feat);
    float4 v = __ldg(&f4[s * 16 + q]);
    float4 m = make_float4(wt * v.x, wt * v.y, wt * v.z, wt * v.w);

    float4* a4 = reinterpret_cast<float4*>(g_agg) + (t * 16 + q);
    atomicAdd(a4, m);        // sm_90+: vector fp32 atomic -> RED.E.ADD.F32.V4
}

// ---------------------------------------------------------------------------
// Kernel 3: out = relu(agg @ W + b)
// 64x64 block tile, 256 threads, 4 rows x 4 cols register tile per thread.
// Both operands read from smem as float4 -> 8 LDS.128 per 64 FMAs.
// ---------------------------------------------------------------------------
__global__ __launch_bounds__(256) void gemm_bias_relu_kernel(
        const float* __restrict__ W,
        const float* __restrict__ b,
        float* __restrict__ out) {
    __shared__ float Ws[D * D];              // [k][c] row-major
    __shared__ float As[64 * D];             // [r][k] row-major

    int tid = threadIdx.x;
    int row0 = blockIdx.x * 64;

    // Load W tile (4096 floats = 1024 float4), coalesced.
    const float4* W4 = reinterpret_cast<const float4*>(W);
    float4* Ws4 = reinterpret_cast<float4*>(Ws);
    #pragma unroll
    for (int i = tid; i < 1024; i += 256) Ws4[i] = W4[i];

    // Load 64 agg rows (guarded for the final partial block).
    const float4* A4 = reinterpret_cast<const float4*>(g_agg) + row0 * 16;
    float4* As4 = reinterpret_cast<float4*>(As);
    #pragma unroll
    for (int i = tid; i < 1024; i += 256) {
        int r = i >> 4;                       // row within tile
        As4[i] = (row0 + r < N_NODES) ? A4[i]
                                      : make_float4(0.f, 0.f, 0.f, 0.f);
    }
    __syncthreads();

    int tx = tid & 15;            // column group: cols c0..c0+3
    int ty = tid >> 4;            // row group:    rows r0..r0+3
    int c0 = tx * 4;
    int r0 = ty * 4;

    float4 bv = __ldg(&reinterpret_cast<const float4*>(b)[tx]);
    float4 acc[4];
    #pragma unroll
    for (int i = 0; i < 4; i++) acc[i] = bv;

    #pragma unroll
    for (int k0 = 0; k0 < D; k0 += 4) {
        float4 wr0 = *reinterpret_cast<const float4*>(&Ws[(k0 + 0) * D + c0]);
        float4 wr1 = *reinterpret_cast<const float4*>(&Ws[(k0 + 1) * D + c0]);
        float4 wr2 = *reinterpret_cast<const float4*>(&Ws[(k0 + 2) * D + c0]);
        float4 wr3 = *reinterpret_cast<const float4*>(&Ws[(k0 + 3) * D + c0]);
        #pragma unroll
        for (int i = 0; i < 4; i++) {
            float4 av = *reinterpret_cast<const float4*>(&As[(r0 + i) * D + k0]);
            acc[i].x = fmaf(av.x, wr0.x, acc[i].x);
            acc[i].y = fmaf(av.x, wr0.y, acc[i].y);
            acc[i].z = fmaf(av.x, wr0.z, acc[i].z);
            acc[i].w = fmaf(av.x, wr0.w, acc[i].w);

            acc[i].x = fmaf(av.y, wr1.x, acc[i].x);
            acc[i].y = fmaf(av.y, wr1.y, acc[i].y);
            acc[i].z = fmaf(av.y, wr1.z, acc[i].z);
            acc[i].w = fmaf(av.y, wr1.w, acc[i].w);

            acc[i].x = fmaf(av.z, wr2.x, acc[i].x);
            acc[i].y = fmaf(av.z, wr2.y, acc[i].y);
            acc[i].z = fmaf(av.z, wr2.z, acc[i].z);
            acc[i].w = fmaf(av.z, wr2.w, acc[i].w);

            acc[i].x = fmaf(av.w, wr3.x, acc[i].x);
            acc[i].y = fmaf(av.w, wr3.y, acc[i].y);
            acc[i].z = fmaf(av.w, wr3.z, acc[i].z);
            acc[i].w = fmaf(av.w, wr3.w, acc[i].w);
        }
    }

    #pragma unroll
    for (int i = 0; i < 4; i++) {
        int row = row0 + r0 + i;
        if (row < N_NODES) {
            float4 r;
            r.x = fmaxf(acc[i].x, 0.f);
            r.y = fmaxf(acc[i].y, 0.f);
            r.z = fmaxf(acc[i].z, 0.f);
            r.w = fmaxf(acc[i].w, 0.f);
            reinterpret_cast<float4*>(out)[row * 16 + c0 / 4] = r;
        }
    }
}

// ---------------------------------------------------------------------------
// Launch
// ---------------------------------------------------------------------------
extern "C" void kernel_launch(void* const* d_in, const int* in_sizes, int n_in,
                              void* d_out, int out_size) {
    const float* features = (const float*)d_in[0];   // [N_NODES, D]
    const int*   edge_src = (const int*)  d_in[1];   // [N_EDGES]
    const int*   edge_dst = (const int*)  d_in[2];   // [N_EDGES]
    const float* edge_w   = (const float*)d_in[3];   // [N_EDGES]
    const float* W        = (const float*)d_in[4];   // [D, D]
    const float* b        = (const float*)d_in[5];   // [1, D]
    float* out = (float*)d_out;                      // [N_NODES, D]

    // 1) zero scratch
    {
        int n4 = (N_NODES * D) / 4;
        int threads = 256;
        int blocks = (n4 + threads - 1) / threads;
        zero_kernel<<<blocks, threads>>>();
    }

    // 2) scatter-add messages (float4 atomics)
    {
        int total = N_EDGES * 16;
        int threads = 256;
        int blocks = (total + threads - 1) / threads;
        scatter_kernel<<<blocks, threads>>>(features, edge_src, edge_dst, edge_w);
    }

    // 3) dense transform + bias + relu
    {
        int blocks = (N_NODES + 63) / 64;
        gemm_bias_relu_kernel<<<blocks, 256>>>(W, b, out);
    }
}

// round 3
// speedup vs baseline: 2.9687x; 1.0688x over previous
#include <cuda_runtime.h>

#define N_NODES 100000
#define N_EDGES 1600000
#define D 64

#define SCAN_BLK 1024
#define SCAN_NBLK 98                 // 98*1024 = 100352 >= 100000
#define SCAN_PAD (SCAN_NBLK * SCAN_BLK)

// Scratch (static __device__ arrays: allowed).
__device__ int   g_count[SCAN_PAD];
__device__ int   g_excl[SCAN_PAD];
__device__ int   g_bsum[SCAN_NBLK];
__device__ int   g_bpre[SCAN_NBLK];
__device__ int   g_rowptr[N_NODES];
__device__ int   g_cursor[N_NODES];
__device__ int2  g_edges[N_EDGES];    // (src, w-as-int) binned by dst
__device__ float g_agg[N_NODES * D];

// ---------------------------------------------------------------------------
// 1) zero histogram counters
// ---------------------------------------------------------------------------
__global__ void zero_counts_kernel() {
    int i = blockIdx.x * blockDim.x + threadIdx.x;
    if (i < SCAN_PAD) g_count[i] = 0;
}

// ---------------------------------------------------------------------------
// 2) histogram of destination nodes
// ---------------------------------------------------------------------------
__global__ void hist_kernel(const int* __restrict__ dst) {
    int e = blockIdx.x * blockDim.x + threadIdx.x;
    if (e < N_EDGES) atomicAdd(&g_count[__ldg(&dst[e])], 1);
}

// ---------------------------------------------------------------------------
// 3a) per-block exclusive scan (1024 elements per block) + block totals
// ---------------------------------------------------------------------------
__global__ __launch_bounds__(SCAN_BLK) void scan_a_kernel() {
    __shared__ int s[SCAN_BLK];
    int t = threadIdx.x;
    int gid = blockIdx.x * SCAN_BLK + t;
    int c = g_count[gid];
    s[t] = c;
    __syncthreads();
    #pragma unroll
    for (int off = 1; off < SCAN_BLK; off <<= 1) {
        int v = (t >= off) ? s[t - off] : 0;
        __syncthreads();
        s[t] += v;
        __syncthreads();
    }
    g_excl[gid] = s[t] - c;                   // exclusive
    if (t == SCAN_BLK - 1) g_bsum[blockIdx.x] = s[t];
}

// 3b) scan block totals (single block)
__global__ void scan_b_kernel() {
    __shared__ int s[SCAN_NBLK];
    int t = threadIdx.x;
    if (t < SCAN_NBLK) s[t] = g_bsum[t];
    __syncthreads();
    if (t == 0) {
        int run = 0;
        for (int i = 0; i < SCAN_NBLK; i++) { int v = s[i]; s[i] = run; run += v; }
    }
    __syncthreads();
    if (t < SCAN_NBLK) g_bpre[t] = s[t];
}

// 3c) add block prefixes -> row_ptr, and init cursors
__global__ void scan_c_kernel() {
    int i = blockIdx.x * blockDim.x + threadIdx.x;
    if (i < N_NODES) {
        int v = g_excl[i] + g_bpre[i >> 10];
        g_rowptr[i] = v;
        g_cursor[i] = v;
    }
}

// ---------------------------------------------------------------------------
// 4) bin edges by destination: g_edges[pos] = (src, w)
// ---------------------------------------------------------------------------
__global__ void bin_kernel(const int*   __restrict__ src,
                           const int*   __restrict__ dst,
                           const float* __restrict__ w) {
    int e = blockIdx.x * blockDim.x + threadIdx.x;
    if (e >= N_EDGES) return;
    int t = __ldg(&dst[e]);
    int pos = atomicAdd(&g_cursor[t], 1);
    g_edges[pos] = make_int2(__ldg(&src[e]), __float_as_int(__ldg(&w[e])));
}

// ---------------------------------------------------------------------------
// 5) gather-reduce: one warp per destination node, no atomics.
//    Lane l accumulates feature columns (2l, 2l+1) as float2.
// ---------------------------------------------------------------------------
__global__ __launch_bounds__(256) void gather_kernel(
        const float* __restrict__ feat) {
    int gtid = blockIdx.x * blockDim.x + threadIdx.x;
    int node = gtid >> 5;
    int lane = gtid & 31;
    if (node >= N_NODES) return;

    int beg = __ldg(&g_rowptr[node]);
    int end = (node == N_NODES - 1) ? N_EDGES : __ldg(&g_rowptr[node + 1]);

    const float2* f2 = reinterpret_cast<const float2*>(feat);
    float2 acc = make_float2(0.f, 0.f);

    int j = beg;
    // unroll-by-2: two independent load chains for MLP
    for (; j + 1 < end; j += 2) {
        int2 p0 = g_edges[j];
        int2 p1 = g_edges[j + 1];
        float2 f0 = __ldg(&f2[p0.x * 32 + lane]);
        float2 f1 = __ldg(&f2[p1.x * 32 + lane]);
        float w0 = __int_as_float(p0.y);
        float w1 = __int_as_float(p1.y);
        acc.x = fmaf(w0, f0.x, acc.x);
        acc.y = fmaf(w0, f0.y, acc.y);
        acc.x = fmaf(w1, f1.x, acc.x);
        acc.y = fmaf(w1, f1.y, acc.y);
    }
    if (j < end) {
        int2 p = g_edges[j];
        float2 f = __ldg(&f2[p.x * 32 + lane]);
        float wv = __int_as_float(p.y);
        acc.x = fmaf(wv, f.x, acc.x);
        acc.y = fmaf(wv, f.y, acc.y);
    }

    reinterpret_cast<float2*>(g_agg)[node * 32 + lane] = acc;
}

// ---------------------------------------------------------------------------
// 6) out = relu(agg @ W + b)  -- 64x64 tile, 4x4 register tile per thread
// ---------------------------------------------------------------------------
__global__ __launch_bounds__(256) void gemm_bias_relu_kernel(
        const float* __restrict__ W,
        const float* __restrict__ b,
        float* __restrict__ out) {
    __shared__ float Ws[D * D];
    __shared__ float As[64 * D];

    int tid = threadIdx.x;
    int row0 = blockIdx.x * 64;

    const float4* W4 = reinterpret_cast<const float4*>(W);
    float4* Ws4 = reinterpret_cast<float4*>(Ws);
    #pragma unroll
    for (int i = tid; i < 1024; i += 256) Ws4[i] = W4[i];

    const float4* A4 = reinterpret_cast<const float4*>(g_agg) + row0 * 16;
    float4* As4 = reinterpret_cast<float4*>(As);
    #pragma unroll
    for (int i = tid; i < 1024; i += 256) {
        int r = i >> 4;
        As4[i] = (row0 + r < N_NODES) ? A4[i]
                                      : make_float4(0.f, 0.f, 0.f, 0.f);
    }
    __syncthreads();

    int tx = tid & 15;
    int ty = tid >> 4;
    int c0 = tx * 4;
    int r0 = ty * 4;

    float4 bv = __ldg(&reinterpret_cast<const float4*>(b)[tx]);
    float4 acc[4];
    #pragma unroll
    for (int i = 0; i < 4; i++) acc[i] = bv;

    #pragma unroll
    for (int k0 = 0; k0 < D; k0 += 4) {
        float4 wr0 = *reinterpret_cast<const float4*>(&Ws[(k0 + 0) * D + c0]);
        float4 wr1 = *reinterpret_cast<const float4*>(&Ws[(k0 + 1) * D + c0]);
        float4 wr2 = *reinterpret_cast<const float4*>(&Ws[(k0 + 2) * D + c0]);
        float4 wr3 = *reinterpret_cast<const float4*>(&Ws[(k0 + 3) * D + c0]);
        #pragma unroll
        for (int i = 0; i < 4; i++) {
            float4 av = *reinterpret_cast<const float4*>(&As[(r0 + i) * D + k0]);
            acc[i].x = fmaf(av.x, wr0.x, acc[i].x);
            acc[i].y = fmaf(av.x, wr0.y, acc[i].y);
            acc[i].z = fmaf(av.x, wr0.z, acc[i].z);
            acc[i].w = fmaf(av.x, wr0.w, acc[i].w);

            acc[i].x = fmaf(av.y, wr1.x, acc[i].x);
            acc[i].y = fmaf(av.y, wr1.y, acc[i].y);
            acc[i].z = fmaf(av.y, wr1.z, acc[i].z);
            acc[i].w = fmaf(av.y, wr1.w, acc[i].w);

            acc[i].x = fmaf(av.z, wr2.x, acc[i].x);
            acc[i].y = fmaf(av.z, wr2.y, acc[i].y);
            acc[i].z = fmaf(av.z, wr2.z, acc[i].z);
            acc[i].w = fmaf(av.z, wr2.w, acc[i].w);

            acc[i].x = fmaf(av.w, wr3.x, acc[i].x);
            acc[i].y = fmaf(av.w, wr3.y, acc[i].y);
            acc[i].z = fmaf(av.w, wr3.z, acc[i].z);
            acc[i].w = fmaf(av.w, wr3.w, acc[i].w);
        }
    }

    #pragma unroll
    for (int i = 0; i < 4; i++) {
        int row = row0 + r0 + i;
        if (row < N_NODES) {
            float4 r;
            r.x = fmaxf(acc[i].x, 0.f);
            r.y = fmaxf(acc[i].y, 0.f);
            r.z = fmaxf(acc[i].z, 0.f);
            r.w = fmaxf(acc[i].w, 0.f);
            reinterpret_cast<float4*>(out)[row * 16 + c0 / 4] = r;
        }
    }
}

// ---------------------------------------------------------------------------
// Launch
// ---------------------------------------------------------------------------
extern "C" void kernel_launch(void* const* d_in, const int* in_sizes, int n_in,
                              void* d_out, int out_size) {
    const float* features = (const float*)d_in[0];   // [N_NODES, D]
    const int*   edge_src = (const int*)  d_in[1];   // [N_EDGES]
    const int*   edge_dst = (const int*)  d_in[2];   // [N_EDGES]
    const float* edge_w   = (const float*)d_in[3];   // [N_EDGES]
    const float* W        = (const float*)d_in[4];   // [D, D]
    const float* b        = (const float*)d_in[5];   // [1, D]
    float* out = (float*)d_out;                      // [N_NODES, D]

    zero_counts_kernel<<<(SCAN_PAD + 255) / 256, 256>>>();
    hist_kernel<<<(N_EDGES + 255) / 256, 256>>>(edge_dst);
    scan_a_kernel<<<SCAN_NBLK, SCAN_BLK>>>();
    scan_b_kernel<<<1, 128>>>();
    scan_c_kernel<<<(N_NODES + 255) / 256, 256>>>();
    bin_kernel<<<(N_EDGES + 255) / 256, 256>>>(edge_src, edge_dst, edge_w);

    {
        long long threads_total = (long long)N_NODES * 32;
        int blocks = (int)((threads_total + 255) / 256);
        gather_kernel<<<blocks, 256>>>(features);
    }

    gemm_bias_relu_kernel<<<(N_NODES + 63) / 64, 256>>>(W, b, out);
}

// round 4
// speedup vs baseline: 3.0117x; 1.0145x over previous
#include <cuda_runtime.h>

#define N_NODES 100000
#define N_EDGES 1600000
#define D 64

#define SCAN_BLK 1024
#define SCAN_NBLK 98                 // 98*1024 = 100352 >= 100000
#define SCAN_PAD (SCAN_NBLK * SCAN_BLK)

// Scratch (static __device__ arrays: allowed).
__device__ int   g_count[SCAN_PAD];
__device__ int   g_excl[SCAN_PAD];
__device__ int   g_bsum[SCAN_NBLK];
__device__ int   g_rowptr[N_NODES];
__device__ int   g_cursor[N_NODES];
__device__ int2  g_edges[N_EDGES];    // (src, w-as-int) binned by dst
__device__ float g_Z[N_NODES * D];    // Z = X @ W (pre-transformed features)

// ---------------------------------------------------------------------------
// 1) histogram of destination nodes (counters zeroed by memset node)
// ---------------------------------------------------------------------------
__global__ void hist_kernel(const int* __restrict__ dst) {
    int e = blockIdx.x * blockDim.x + threadIdx.x;
    if (e < N_EDGES) atomicAdd(&g_count[__ldg(&dst[e])], 1);
}

// ---------------------------------------------------------------------------
// 2a) per-block exclusive scan (1024 elements per block) + block totals
// ---------------------------------------------------------------------------
__global__ __launch_bounds__(SCAN_BLK) void scan_a_kernel() {
    __shared__ int s[SCAN_BLK];
    int t = threadIdx.x;
    int gid = blockIdx.x * SCAN_BLK + t;
    int c = g_count[gid];
    s[t] = c;
    __syncthreads();
    #pragma unroll
    for (int off = 1; off < SCAN_BLK; off <<= 1) {
        int v = (t >= off) ? s[t - off] : 0;
        __syncthreads();
        s[t] += v;
        __syncthreads();
    }
    g_excl[gid] = s[t] - c;                   // exclusive
    if (t == SCAN_BLK - 1) g_bsum[blockIdx.x] = s[t];
}

// 2b) finalize row_ptr: add prefix of block sums. Each block covers 256
//     nodes, all inside ONE scan_a block (256 | 1024), so it needs a single
//     prefix value, computed in-block from the 98 bsum entries.
__global__ __launch_bounds__(256) void scan_c_kernel() {
    __shared__ int s[SCAN_NBLK];
    __shared__ int prefix;
    int t = threadIdx.x;
    int sblk = blockIdx.x >> 2;               // which scan_a block these nodes are in
    if (t < SCAN_NBLK) s[t] = g_bsum[t];
    __syncthreads();
    if (t == 0) {
        int run = 0;
        for (int i = 0; i < sblk; i++) run += s[i];
        prefix = run;
    }
    __syncthreads();
    int i = blockIdx.x * 256 + t;
    if (i < N_NODES) {
        int v = g_excl[i] + prefix;
        g_rowptr[i] = v;
        g_cursor[i] = v;
    }
}

// ---------------------------------------------------------------------------
// 3) bin edges by destination: g_edges[pos] = (src, w)
// ---------------------------------------------------------------------------
__global__ void bin_kernel(const int*   __restrict__ src,
                           const int*   __restrict__ dst,
                           const float* __restrict__ w) {
    int e = blockIdx.x * blockDim.x + threadIdx.x;
    if (e >= N_EDGES) return;
    int t = __ldg(&dst[e]);
    int pos = atomicAdd(&g_cursor[t], 1);
    g_edges[pos] = make_int2(__ldg(&src[e]), __float_as_int(__ldg(&w[e])));
}

// ---------------------------------------------------------------------------
// 4) Z = X @ W   (64x64 tile, 4x4 register tile per thread, no bias/relu)
// ---------------------------------------------------------------------------
__global__ __launch_bounds__(256) void gemm_z_kernel(
        const float* __restrict__ X,
        const float* __restrict__ W) {
    __shared__ float Ws[D * D];
    __shared__ float As[64 * D];

    int tid = threadIdx.x;
    int row0 = blockIdx.x * 64;

    const float4* W4 = reinterpret_cast<const float4*>(W);
    float4* Ws4 = reinterpret_cast<float4*>(Ws);
    #pragma unroll
    for (int i = tid; i < 1024; i += 256) Ws4[i] = W4[i];

    const float4* A4 = reinterpret_cast<const float4*>(X) + row0 * 16;
    float4* As4 = reinterpret_cast<float4*>(As);
    #pragma unroll
    for (int i = tid; i < 1024; i += 256) {
        int r = i >> 4;
        As4[i] = (row0 + r < N_NODES) ? A4[i]
                                      : make_float4(0.f, 0.f, 0.f, 0.f);
    }
    __syncthreads();

    int tx = tid & 15;
    int ty = tid >> 4;
    int c0 = tx * 4;
    int r0 = ty * 4;

    float4 acc[4];
    #pragma unroll
    for (int i = 0; i < 4; i++) acc[i] = make_float4(0.f, 0.f, 0.f, 0.f);

    #pragma unroll
    for (int k0 = 0; k0 < D; k0 += 4) {
        float4 wr0 = *reinterpret_cast<const float4*>(&Ws[(k0 + 0) * D + c0]);
        float4 wr1 = *reinterpret_cast<const float4*>(&Ws[(k0 + 1) * D + c0]);
        float4 wr2 = *reinterpret_cast<const float4*>(&Ws[(k0 + 2) * D + c0]);
        float4 wr3 = *reinterpret_cast<const float4*>(&Ws[(k0 + 3) * D + c0]);
        #pragma unroll
        for (int i = 0; i < 4; i++) {
            float4 av = *reinterpret_cast<const float4*>(&As[(r0 + i) * D + k0]);
            acc[i].x = fmaf(av.x, wr0.x, acc[i].x);
            acc[i].y = fmaf(av.x, wr0.y, acc[i].y);
            acc[i].z = fmaf(av.x, wr0.z, acc[i].z);
            acc[i].w = fmaf(av.x, wr0.w, acc[i].w);

            acc[i].x = fmaf(av.y, wr1.x, acc[i].x);
            acc[i].y = fmaf(av.y, wr1.y, acc[i].y);
            acc[i].z = fmaf(av.y, wr1.z, acc[i].z);
            acc[i].w = fmaf(av.y, wr1.w, acc[i].w);

            acc[i].x = fmaf(av.z, wr2.x, acc[i].x);
            acc[i].y = fmaf(av.z, wr2.y, acc[i].y);
            acc[i].z = fmaf(av.z, wr2.z, acc[i].z);
            acc[i].w = fmaf(av.z, wr2.w, acc[i].w);

            acc[i].x = fmaf(av.w, wr3.x, acc[i].x);
            acc[i].y = fmaf(av.w, wr3.y, acc[i].y);
            acc[i].z = fmaf(av.w, wr3.z, acc[i].z);
            acc[i].w = fmaf(av.w, wr3.w, acc[i].w);
        }
    }

    #pragma unroll
    for (int i = 0; i < 4; i++) {
        int row = row0 + r0 + i;
        if (row < N_NODES) {
            reinterpret_cast<float4*>(g_Z)[row * 16 + c0 / 4] = acc[i];
        }
    }
}

// ---------------------------------------------------------------------------
// 5) gather-reduce over Z + bias + relu -> out.  One warp per destination
//    node, no atomics. Lane l handles output columns (2l, 2l+1).
// ---------------------------------------------------------------------------
__global__ __launch_bounds__(256) void gather_out_kernel(
        const float* __restrict__ b,
        float* __restrict__ out) {
    int gtid = blockIdx.x * blockDim.x + threadIdx.x;
    int node = gtid >> 5;
    int lane = gtid & 31;
    if (node >= N_NODES) return;

    int beg = __ldg(&g_rowptr[node]);
    int end = (node == N_NODES - 1) ? N_EDGES : __ldg(&g_rowptr[node + 1]);

    const float2* z2 = reinterpret_cast<const float2*>(g_Z);
    float2 acc = make_float2(0.f, 0.f);

    int j = beg;
    for (; j + 1 < end; j += 2) {
        int2 p0 = g_edges[j];
        int2 p1 = g_edges[j + 1];
        float2 f0 = __ldg(&z2[p0.x * 32 + lane]);
        float2 f1 = __ldg(&z2[p1.x * 32 + lane]);
        float w0 = __int_as_float(p0.y);
        float w1 = __int_as_float(p1.y);
        acc.x = fmaf(w0, f0.x, acc.x);
        acc.y = fmaf(w0, f0.y, acc.y);
        acc.x = fmaf(w1, f1.x, acc.x);
        acc.y = fmaf(w1, f1.y, acc.y);
    }
    if (j < end) {
        int2 p = g_edges[j];
        float2 f = __ldg(&z2[p.x * 32 + lane]);
        float wv = __int_as_float(p.y);
        acc.x = fmaf(wv, f.x, acc.x);
        acc.y = fmaf(wv, f.y, acc.y);
    }

    float2 bv = __ldg(&reinterpret_cast<const float2*>(b)[lane]);
    float2 r;
    r.x = fmaxf(acc.x + bv.x, 0.f);
    r.y = fmaxf(acc.y + bv.y, 0.f);
    reinterpret_cast<float2*>(out)[node * 32 + lane] = r;
}

// ---------------------------------------------------------------------------
// Launch
// ---------------------------------------------------------------------------
extern "C" void kernel_launch(void* const* d_in, const int* in_sizes, int n_in,
                              void* d_out, int out_size) {
    const float* features = (const float*)d_in[0];   // [N_NODES, D]
    const int*   edge_src = (const int*)  d_in[1];   // [N_EDGES]
    const int*   edge_dst = (const int*)  d_in[2];   // [N_EDGES]
    const float* edge_w   = (const float*)d_in[3];   // [N_EDGES]
    const float* W        = (const float*)d_in[4];   // [D, D]
    const float* b        = (const float*)d_in[5];   // [1, D]
    float* out = (float*)d_out;                      // [N_NODES, D]

    // zero histogram counters via memset node
    void* count_ptr = nullptr;
    cudaGetSymbolAddress(&count_ptr, g_count);
    cudaMemsetAsync(count_ptr, 0, SCAN_PAD * sizeof(int));

    hist_kernel<<<(N_EDGES + 255) / 256, 256>>>(edge_dst);
    scan_a_kernel<<<SCAN_NBLK, SCAN_BLK>>>();
    scan_c_kernel<<<(N_NODES + 255) / 256, 256>>>();
    bin_kernel<<<(N_EDGES + 255) / 256, 256>>>(edge_src, edge_dst, edge_w);

    gemm_z_kernel<<<(N_NODES + 63) / 64, 256>>>(features, W);

    {
        long long threads_total = (long long)N_NODES * 32;
        int blocks = (int)((threads_total + 255) / 256);
        gather_out_kernel<<<blocks, 256>>>(b, out);
    }
}

// round 5
// speedup vs baseline: 3.0689x; 1.0190x over previous
#include <cuda_runtime.h>

#define N_NODES 100000
#define N_EDGES 1600000
#define D 64

#define SCAN_BLK 1024
#define SCAN_NBLK 98                 // 98*1024 = 100352 >= 100000
#define SCAN_PAD (SCAN_NBLK * SCAN_BLK)

// Scratch (static __device__ arrays: allowed).
__device__ int   g_count[SCAN_PAD];
__device__ int   g_excl[SCAN_PAD];
__device__ int   g_bsum[SCAN_NBLK];
__device__ int   g_rowptr[N_NODES];
__device__ int   g_cursor[N_NODES];
__device__ int2  g_edges[N_EDGES];    // (src, w-as-int) binned by dst
__device__ float g_Z[N_NODES * D];    // Z = X @ W (pre-transformed features)

// ---------------------------------------------------------------------------
// 1) histogram of destination nodes — 4 edges/thread for atomic MLP.
// ---------------------------------------------------------------------------
__global__ __launch_bounds__(256) void hist_kernel(const int* __restrict__ dst) {
    int e0 = (blockIdx.x * blockDim.x + threadIdx.x) * 4;
    if (e0 + 3 < N_EDGES) {
        int4 t = *reinterpret_cast<const int4*>(&dst[e0]);
        atomicAdd(&g_count[t.x], 1);
        atomicAdd(&g_count[t.y], 1);
        atomicAdd(&g_count[t.z], 1);
        atomicAdd(&g_count[t.w], 1);
    } else {
        for (int e = e0; e < N_EDGES; e++) atomicAdd(&g_count[__ldg(&dst[e])], 1);
    }
}

// ---------------------------------------------------------------------------
// 2a) per-block exclusive scan (1024 elements per block) + block totals
// ---------------------------------------------------------------------------
__global__ __launch_bounds__(SCAN_BLK) void scan_a_kernel() {
    __shared__ int s[SCAN_BLK];
    int t = threadIdx.x;
    int gid = blockIdx.x * SCAN_BLK + t;
    int c = g_count[gid];
    s[t] = c;
    __syncthreads();
    #pragma unroll
    for (int off = 1; off < SCAN_BLK; off <<= 1) {
        int v = (t >= off) ? s[t - off] : 0;
        __syncthreads();
        s[t] += v;
        __syncthreads();
    }
    g_excl[gid] = s[t] - c;                   // exclusive
    if (t == SCAN_BLK - 1) g_bsum[blockIdx.x] = s[t];
}

// 2b) finalize row_ptr: add prefix of block sums. Each block covers 256
//     nodes, all inside ONE scan_a block (256 | 1024).
__global__ __launch_bounds__(256) void scan_c_kernel() {
    __shared__ int s[SCAN_NBLK];
    __shared__ int prefix;
    int t = threadIdx.x;
    int sblk = blockIdx.x >> 2;
    if (t < SCAN_NBLK) s[t] = g_bsum[t];
    __syncthreads();
    if (t == 0) {
        int run = 0;
        for (int i = 0; i < sblk; i++) run += s[i];
        prefix = run;
    }
    __syncthreads();
    int i = blockIdx.x * 256 + t;
    if (i < N_NODES) {
        int v = g_excl[i] + prefix;
        g_rowptr[i] = v;
        g_cursor[i] = v;
    }
}

// ---------------------------------------------------------------------------
// 3) bin edges by destination — 4 edges/thread: coalesced int4/float4 loads,
//    4 independent atomic->store chains in flight.
// ---------------------------------------------------------------------------
__global__ __launch_bounds__(256) void bin_kernel(
        const int*   __restrict__ src,
        const int*   __restrict__ dst,
        const float* __restrict__ w) {
    int e0 = (blockIdx.x * blockDim.x + threadIdx.x) * 4;
    if (e0 + 3 < N_EDGES) {
        int4   s = *reinterpret_cast<const int4*>(&src[e0]);
        int4   t = *reinterpret_cast<const int4*>(&dst[e0]);
        float4 v = *reinterpret_cast<const float4*>(&w[e0]);
        int p0 = atomicAdd(&g_cursor[t.x], 1);
        int p1 = atomicAdd(&g_cursor[t.y], 1);
        int p2 = atomicAdd(&g_cursor[t.z], 1);
        int p3 = atomicAdd(&g_cursor[t.w], 1);
        g_edges[p0] = make_int2(s.x, __float_as_int(v.x));
        g_edges[p1] = make_int2(s.y, __float_as_int(v.y));
        g_edges[p2] = make_int2(s.z, __float_as_int(v.z));
        g_edges[p3] = make_int2(s.w, __float_as_int(v.w));
    } else {
        for (int e = e0; e < N_EDGES; e++) {
            int t = __ldg(&dst[e]);
            int pos = atomicAdd(&g_cursor[t], 1);
            g_edges[pos] = make_int2(__ldg(&src[e]), __float_as_int(__ldg(&w[e])));
        }
    }
}

// ---------------------------------------------------------------------------
// 4) Z = X @ W   (64x64 tile, 4x4 register tile per thread)
// ---------------------------------------------------------------------------
__global__ __launch_bounds__(256) void gemm_z_kernel(
        const float* __restrict__ X,
        const float* __restrict__ W) {
    __shared__ float Ws[D * D];
    __shared__ float As[64 * D];

    int tid = threadIdx.x;
    int row0 = blockIdx.x * 64;

    const float4* W4 = reinterpret_cast<const float4*>(W);
    float4* Ws4 = reinterpret_cast<float4*>(Ws);
    #pragma unroll
    for (int i = tid; i < 1024; i += 256) Ws4[i] = W4[i];

    const float4* A4 = reinterpret_cast<const float4*>(X) + row0 * 16;
    float4* As4 = reinterpret_cast<float4*>(As);
    #pragma unroll
    for (int i = tid; i < 1024; i += 256) {
        int r = i >> 4;
        As4[i] = (row0 + r < N_NODES) ? A4[i]
                                      : make_float4(0.f, 0.f, 0.f, 0.f);
    }
    __syncthreads();

    int tx = tid & 15;
    int ty = tid >> 4;
    int c0 = tx * 4;
    int r0 = ty * 4;

    float4 acc[4];
    #pragma unroll
    for (int i = 0; i < 4; i++) acc[i] = make_float4(0.f, 0.f, 0.f, 0.f);

    #pragma unroll
    for (int k0 = 0; k0 < D; k0 += 4) {
        float4 wr0 = *reinterpret_cast<const float4*>(&Ws[(k0 + 0) * D + c0]);
        float4 wr1 = *reinterpret_cast<const float4*>(&Ws[(k0 + 1) * D + c0]);
        float4 wr2 = *reinterpret_cast<const float4*>(&Ws[(k0 + 2) * D + c0]);
        float4 wr3 = *reinterpret_cast<const float4*>(&Ws[(k0 + 3) * D + c0]);
        #pragma unroll
        for (int i = 0; i < 4; i++) {
            float4 av = *reinterpret_cast<const float4*>(&As[(r0 + i) * D + k0]);
            acc[i].x = fmaf(av.x, wr0.x, acc[i].x);
            acc[i].y = fmaf(av.x, wr0.y, acc[i].y);
            acc[i].z = fmaf(av.x, wr0.z, acc[i].z);
            acc[i].w = fmaf(av.x, wr0.w, acc[i].w);

            acc[i].x = fmaf(av.y, wr1.x, acc[i].x);
            acc[i].y = fmaf(av.y, wr1.y, acc[i].y);
            acc[i].z = fmaf(av.y, wr1.z, acc[i].z);
            acc[i].w = fmaf(av.y, wr1.w, acc[i].w);

            acc[i].x = fmaf(av.z, wr2.x, acc[i].x);
            acc[i].y = fmaf(av.z, wr2.y, acc[i].y);
            acc[i].z = fmaf(av.z, wr2.z, acc[i].z);
            acc[i].w = fmaf(av.z, wr2.w, acc[i].w);

            acc[i].x = fmaf(av.w, wr3.x, acc[i].x);
            acc[i].y = fmaf(av.w, wr3.y, acc[i].y);
            acc[i].z = fmaf(av.w, wr3.z, acc[i].z);
            acc[i].w = fmaf(av.w, wr3.w, acc[i].w);
        }
    }

    #pragma unroll
    for (int i = 0; i < 4; i++) {
        int row = row0 + r0 + i;
        if (row < N_NODES) {
            reinterpret_cast<float4*>(g_Z)[row * 16 + c0 / 4] = acc[i];
        }
    }
}

// ---------------------------------------------------------------------------
// 5) gather-reduce over Z + bias + relu -> out.  One warp per node.
//    Half-warps interleave edges (even/odd); each lane loads float4 so a
//    half-warp covers one full 256B row. Partial sums combined by shfl.
// ---------------------------------------------------------------------------
__global__ __launch_bounds__(256) void gather_out_kernel(
        const float* __restrict__ b,
        float* __restrict__ out) {
    int gtid = blockIdx.x * blockDim.x + threadIdx.x;
    int node = gtid >> 5;
    int lane = gtid & 31;
    if (node >= N_NODES) return;
    int half = lane >> 4;        // 0: even edges, 1: odd edges
    int l    = lane & 15;        // float4 chunk within row

    int beg = __ldg(&g_rowptr[node]);
    int end = (node == N_NODES - 1) ? N_EDGES : __ldg(&g_rowptr[node + 1]);

    const float4* z4 = reinterpret_cast<const float4*>(g_Z);
    float4 acc = make_float4(0.f, 0.f, 0.f, 0.f);

    for (int j = beg + half; j < end; j += 2) {
        int2 p = g_edges[j];
        float4 f = __ldg(&z4[p.x * 16 + l]);
        float wv = __int_as_float(p.y);
        acc.x = fmaf(wv, f.x, acc.x);
        acc.y = fmaf(wv, f.y, acc.y);
        acc.z = fmaf(wv, f.z, acc.z);
        acc.w = fmaf(wv, f.w, acc.w);
    }

    // combine the two half-warp partial sums
    acc.x += __shfl_xor_sync(0xFFFFFFFF, acc.x, 16);
    acc.y += __shfl_xor_sync(0xFFFFFFFF, acc.y, 16);
    acc.z += __shfl_xor_sync(0xFFFFFFFF, acc.z, 16);
    acc.w += __shfl_xor_sync(0xFFFFFFFF, acc.w, 16);

    if (half == 0) {
        float4 bv = __ldg(&reinterpret_cast<const float4*>(b)[l]);
        float4 r;
        r.x = fmaxf(acc.x + bv.x, 0.f);
        r.y = fmaxf(acc.y + bv.y, 0.f);
        r.z = fmaxf(acc.z + bv.z, 0.f);
        r.w = fmaxf(acc.w + bv.w, 0.f);
        reinterpret_cast<float4*>(out)[node * 16 + l] = r;
    }
}

// ---------------------------------------------------------------------------
// Launch
// ---------------------------------------------------------------------------
extern "C" void kernel_launch(void* const* d_in, const int* in_sizes, int n_in,
                              void* d_out, int out_size) {
    const float* features = (const float*)d_in[0];   // [N_NODES, D]
    const int*   edge_src = (const int*)  d_in[1];   // [N_EDGES]
    const int*   edge_dst = (const int*)  d_in[2];   // [N_EDGES]
    const float* edge_w   = (const float*)d_in[3];   // [N_EDGES]
    const float* W        = (const float*)d_in[4];   // [D, D]
    const float* b        = (const float*)d_in[5];   // [1, D]
    float* out = (float*)d_out;                      // [N_NODES, D]

    // zero histogram counters via memset node
    void* count_ptr = nullptr;
    cudaGetSymbolAddress(&count_ptr, g_count);
    cudaMemsetAsync(count_ptr, 0, SCAN_PAD * sizeof(int));

    {
        int threads_total = (N_EDGES + 3) / 4;           // 400000
        hist_kernel<<<(threads_total + 255) / 256, 256>>>(edge_dst);
    }
    scan_a_kernel<<<SCAN_NBLK, SCAN_BLK>>>();
    scan_c_kernel<<<(N_NODES + 255) / 256, 256>>>();
    {
        int threads_total = (N_EDGES + 3) / 4;
        bin_kernel<<<(threads_total + 255) / 256, 256>>>(edge_src, edge_dst, edge_w);
    }

    gemm_z_kernel<<<(N_NODES + 63) / 64, 256>>>(features, W);

    {
        long long threads_total = (long long)N_NODES * 32;
        int blocks = (int)((threads_total + 255) / 256);
        gather_out_kernel<<<blocks, 256>>>(b, out);
    }
}

// round 6
// speedup vs baseline: 3.3834x; 1.1025x over previous
#include <cuda_runtime.h>

#define N_NODES 100000
#define N_EDGES 1600000
#define D 64

#define SCAN_BLK 1024
#define SCAN_NBLK 98                 // 98*1024 = 100352 >= 100000
#define SCAN_PAD (SCAN_NBLK * SCAN_BLK)

#define BIN_BLOCKS  1563             // 1563*256*4 = 1600512 >= N_EDGES
#define GEMM_BLOCKS 1563             // 1563*64 = 100032 >= N_NODES

// Scratch (static __device__ arrays: allowed).
__device__ int   g_count[SCAN_PAD];
__device__ int   g_excl[SCAN_PAD];
__device__ int   g_bsum[SCAN_NBLK];
__device__ int   g_rowptr[N_NODES];
__device__ int   g_cursor[N_NODES];
__device__ int2  g_edges[N_EDGES];    // (src, w-as-int) binned by dst
__device__ float g_Z[N_NODES * D];    // Z = X @ W (pre-transformed features)

// ---------------------------------------------------------------------------
// 1) histogram of destination nodes — 4 edges/thread.
// ---------------------------------------------------------------------------
__global__ __launch_bounds__(256) void hist_kernel(const int* __restrict__ dst) {
    int e0 = (blockIdx.x * blockDim.x + threadIdx.x) * 4;
    if (e0 + 3 < N_EDGES) {
        int4 t = *reinterpret_cast<const int4*>(&dst[e0]);
        atomicAdd(&g_count[t.x], 1);
        atomicAdd(&g_count[t.y], 1);
        atomicAdd(&g_count[t.z], 1);
        atomicAdd(&g_count[t.w], 1);
    } else {
        for (int e = e0; e < N_EDGES; e++) atomicAdd(&g_count[__ldg(&dst[e])], 1);
    }
}

// ---------------------------------------------------------------------------
// 2a) per-block exclusive scan (1024 elements per block) + block totals
// ---------------------------------------------------------------------------
__global__ __launch_bounds__(SCAN_BLK) void scan_a_kernel() {
    __shared__ int s[SCAN_BLK];
    int t = threadIdx.x;
    int gid = blockIdx.x * SCAN_BLK + t;
    int c = g_count[gid];
    s[t] = c;
    __syncthreads();
    #pragma unroll
    for (int off = 1; off < SCAN_BLK; off <<= 1) {
        int v = (t >= off) ? s[t - off] : 0;
        __syncthreads();
        s[t] += v;
        __syncthreads();
    }
    g_excl[gid] = s[t] - c;                   // exclusive
    if (t == SCAN_BLK - 1) g_bsum[blockIdx.x] = s[t];
}

// 2b) finalize row_ptr: add prefix of block sums (256 nodes per block lie
//     inside one scan_a block since 256 | 1024).
__global__ __launch_bounds__(256) void scan_c_kernel() {
    __shared__ int s[SCAN_NBLK];
    __shared__ int prefix;
    int t = threadIdx.x;
    int sblk = blockIdx.x >> 2;
    if (t < SCAN_NBLK) s[t] = g_bsum[t];
    __syncthreads();
    if (t == 0) {
        int run = 0;
        for (int i = 0; i < sblk; i++) run += s[i];
        prefix = run;
    }
    __syncthreads();
    int i = blockIdx.x * 256 + t;
    if (i < N_NODES) {
        int v = g_excl[i] + prefix;
        g_rowptr[i] = v;
        g_cursor[i] = v;
    }
}

// ---------------------------------------------------------------------------
// 3) FUSED bin + gemm.  Even blocks: bin 4 edges/thread (latency-bound,
//    atomic-heavy, SM mostly idle). Odd blocks: one 64x64 Z=X@W tile
//    (FMA-bound). Independent work co-resident on each SM -> overlap.
// ---------------------------------------------------------------------------
__global__ __launch_bounds__(256) void bin_gemm_kernel(
        const int*   __restrict__ src,
        const int*   __restrict__ dst,
        const float* __restrict__ w,
        const float* __restrict__ X,
        const float* __restrict__ W) {
    __shared__ float sm[2 * D * D];          // gemm path only (32 KB)

    int part_id = blockIdx.x >> 1;

    if (blockIdx.x & 1) {
        // ---------------- GEMM tile path ----------------
        float* Ws = sm;                      // [k][c]
        float* As = sm + D * D;              // [r][k]
        int tid = threadIdx.x;
        int row0 = part_id * 64;

        const float4* W4 = reinterpret_cast<const float4*>(W);
        float4* Ws4 = reinterpret_cast<float4*>(Ws);
        #pragma unroll
        for (int i = tid; i < 1024; i += 256) Ws4[i] = W4[i];

        const float4* A4 = reinterpret_cast<const float4*>(X) + row0 * 16;
        float4* As4 = reinterpret_cast<float4*>(As);
        #pragma unroll
        for (int i = tid; i < 1024; i += 256) {
            int r = i >> 4;
            As4[i] = (row0 + r < N_NODES) ? A4[i]
                                          : make_float4(0.f, 0.f, 0.f, 0.f);
        }
        __syncthreads();

        int tx = tid & 15;
        int ty = tid >> 4;
        int c0 = tx * 4;
        int r0 = ty * 4;

        float4 acc[4];
        #pragma unroll
        for (int i = 0; i < 4; i++) acc[i] = make_float4(0.f, 0.f, 0.f, 0.f);

        #pragma unroll
        for (int k0 = 0; k0 < D; k0 += 4) {
            float4 wr0 = *reinterpret_cast<const float4*>(&Ws[(k0 + 0) * D + c0]);
            float4 wr1 = *reinterpret_cast<const float4*>(&Ws[(k0 + 1) * D + c0]);
            float4 wr2 = *reinterpret_cast<const float4*>(&Ws[(k0 + 2) * D + c0]);
            float4 wr3 = *reinterpret_cast<const float4*>(&Ws[(k0 + 3) * D + c0]);
            #pragma unroll
            for (int i = 0; i < 4; i++) {
                float4 av = *reinterpret_cast<const float4*>(&As[(r0 + i) * D + k0]);
                acc[i].x = fmaf(av.x, wr0.x, acc[i].x);
                acc[i].y = fmaf(av.x, wr0.y, acc[i].y);
                acc[i].z = fmaf(av.x, wr0.z, acc[i].z);
                acc[i].w = fmaf(av.x, wr0.w, acc[i].w);

                acc[i].x = fmaf(av.y, wr1.x, acc[i].x);
                acc[i].y = fmaf(av.y, wr1.y, acc[i].y);
                acc[i].z = fmaf(av.y, wr1.z, acc[i].z);
                acc[i].w = fmaf(av.y, wr1.w, acc[i].w);

                acc[i].x = fmaf(av.z, wr2.x, acc[i].x);
                acc[i].y = fmaf(av.z, wr2.y, acc[i].y);
                acc[i].z = fmaf(av.z, wr2.z, acc[i].z);
                acc[i].w = fmaf(av.z, wr2.w, acc[i].w);

                acc[i].x = fmaf(av.w, wr3.x, acc[i].x);
                acc[i].y = fmaf(av.w, wr3.y, acc[i].y);
                acc[i].z = fmaf(av.w, wr3.z, acc[i].z);
                acc[i].w = fmaf(av.w, wr3.w, acc[i].w);
            }
        }

        #pragma unroll
        for (int i = 0; i < 4; i++) {
            int row = row0 + r0 + i;
            if (row < N_NODES) {
                reinterpret_cast<float4*>(g_Z)[row * 16 + c0 / 4] = acc[i];
            }
        }
    } else {
        // ---------------- bin path ----------------
        int e0 = (part_id * 256 + threadIdx.x) * 4;
        if (e0 + 3 < N_EDGES) {
            int4   s = *reinterpret_cast<const int4*>(&src[e0]);
            int4   t = *reinterpret_cast<const int4*>(&dst[e0]);
            float4 v = *reinterpret_cast<const float4*>(&w[e0]);
            int p0 = atomicAdd(&g_cursor[t.x], 1);
            int p1 = atomicAdd(&g_cursor[t.y], 1);
            int p2 = atomicAdd(&g_cursor[t.z], 1);
            int p3 = atomicAdd(&g_cursor[t.w], 1);
            g_edges[p0] = make_int2(s.x, __float_as_int(v.x));
            g_edges[p1] = make_int2(s.y, __float_as_int(v.y));
            g_edges[p2] = make_int2(s.z, __float_as_int(v.z));
            g_edges[p3] = make_int2(s.w, __float_as_int(v.w));
        } else {
            for (int e = e0; e < N_EDGES; e++) {
                int t = __ldg(&dst[e]);
                int pos = atomicAdd(&g_cursor[t], 1);
                g_edges[pos] = make_int2(__ldg(&src[e]),
                                         __float_as_int(__ldg(&w[e])));
            }
        }
    }
}

// ---------------------------------------------------------------------------
// 4) gather-reduce over Z + bias + relu -> out.  One warp per node; two
//    half-warps interleave edges; lanes load float4 (half-warp = full row).
// ---------------------------------------------------------------------------
__global__ __launch_bounds__(256) void gather_out_kernel(
        const float* __restrict__ b,
        float* __restrict__ out) {
    int gtid = blockIdx.x * blockDim.x + threadIdx.x;
    int node = gtid >> 5;
    int lane = gtid & 31;
    if (node >= N_NODES) return;
    int half = lane >> 4;
    int l    = lane & 15;

    int beg = __ldg(&g_rowptr[node]);
    int end = (node == N_NODES - 1) ? N_EDGES : __ldg(&g_rowptr[node + 1]);

    const float4* z4 = reinterpret_cast<const float4*>(g_Z);
    float4 acc = make_float4(0.f, 0.f, 0.f, 0.f);

    for (int j = beg + half; j < end; j += 2) {
        int2 p = g_edges[j];
        float4 f = __ldg(&z4[p.x * 16 + l]);
        float wv = __int_as_float(p.y);
        acc.x = fmaf(wv, f.x, acc.x);
        acc.y = fmaf(wv, f.y, acc.y);
        acc.z = fmaf(wv, f.z, acc.z);
        acc.w = fmaf(wv, f.w, acc.w);
    }

    acc.x += __shfl_xor_sync(0xFFFFFFFF, acc.x, 16);
    acc.y += __shfl_xor_sync(0xFFFFFFFF, acc.y, 16);
    acc.z += __shfl_xor_sync(0xFFFFFFFF, acc.z, 16);
    acc.w += __shfl_xor_sync(0xFFFFFFFF, acc.w, 16);

    if (half == 0) {
        float4 bv = __ldg(&reinterpret_cast<const float4*>(b)[l]);
        float4 r;
        r.x = fmaxf(acc.x + bv.x, 0.f);
        r.y = fmaxf(acc.y + bv.y, 0.f);
        r.z = fmaxf(acc.z + bv.z, 0.f);
        r.w = fmaxf(acc.w + bv.w, 0.f);
        reinterpret_cast<float4*>(out)[node * 16 + l] = r;
    }
}

// ---------------------------------------------------------------------------
// Launch
// ---------------------------------------------------------------------------
extern "C" void kernel_launch(void* const* d_in, const int* in_sizes, int n_in,
                              void* d_out, int out_size) {
    const float* features = (const float*)d_in[0];   // [N_NODES, D]
    const int*   edge_src = (const int*)  d_in[1];   // [N_EDGES]
    const int*   edge_dst = (const int*)  d_in[2];   // [N_EDGES]
    const float* edge_w   = (const float*)d_in[3];   // [N_EDGES]
    const float* W        = (const float*)d_in[4];   // [D, D]
    const float* b        = (const float*)d_in[5];   // [1, D]
    float* out = (float*)d_out;                      // [N_NODES, D]

    void* count_ptr = nullptr;
    cudaGetSymbolAddress(&count_ptr, g_count);
    cudaMemsetAsync(count_ptr, 0, SCAN_PAD * sizeof(int));

    {
        int threads_total = (N_EDGES + 3) / 4;
        hist_kernel<<<(threads_total + 255) / 256, 256>>>(edge_dst);
    }
    scan_a_kernel<<<SCAN_NBLK, SCAN_BLK>>>();
    scan_c_kernel<<<(N_NODES + 255) / 256, 256>>>();

    // fused bin + gemm (even blocks bin, odd blocks gemm)
    bin_gemm_kernel<<<BIN_BLOCKS + GEMM_BLOCKS, 256>>>(
        edge_src, edge_dst, edge_w, features, W);

    {
        long long threads_total = (long long)N_NODES * 32;
        int blocks = (int)((threads_total + 255) / 256);
        gather_out_kernel<<<blocks, 256>>>(b, out);
    }
}